// round 1
// baseline (speedup 1.0000x reference)
#include <cuda_runtime.h>

// Problem constants
#define NB     8
#define NPTS   16384
#define MC     2048
#define KNN    32
#define C1     64
#define C2     128
#define C3     256
#define NC_PER_CTA 8

// Padded shared-memory row sizes (in floats). Padding chosen so rows stay
// 16B-aligned (float4 loads) while shifting bank phase (x%32 == 4 or 8).
#define W2ROW  136
#define W3ROW  264
#define H1ROW  68
#define H2ROW  132

// Shared memory layout (float offsets)
#define OFF_W1   0                       // [3][64] transposed W1
#define OFF_B1   192
#define OFF_B2   256
#define OFF_B3   384
#define OFF_W2   640                     // [64][W2ROW], c-major, 128 used/row
#define OFF_W3   (OFF_W2 + 64*W2ROW)     // [128][W3ROW], c-major, 256 used/row
#define OFF_H1   (OFF_W3 + 128*W3ROW)    // [32][H1ROW]
#define OFF_H2   (OFF_H1 + 32*H1ROW)     // [32][H2ROW]
#define OFF_OUTP (OFF_H2 + 32*H2ROW)     // [4][128] float2 partial maxes
#define SMEM_FLOATS (OFF_OUTP + 1024)
#define SMEM_BYTES  (SMEM_FLOATS * 4)    // 202240 B < 227KB

typedef unsigned long long ull;

// Packed fp32x2 FMA: the only way to hit 128 FP32 MAC/cyc/SM on sm_103a
// (3-reg FFMA is rt=2; ptxas only emits FFMA2 from explicit PTX).
__device__ __forceinline__ ull fma2(ull a, ull b, ull c) {
    ull d;
    asm("fma.rn.f32x2 %0, %1, %2, %3;" : "=l"(d) : "l"(a), "l"(b), "l"(c));
    return d;
}
__device__ __forceinline__ ull pack2(float lo, float hi) {
    ull r;
    asm("mov.b64 %0, {%1, %2};" : "=l"(r) : "f"(lo), "f"(hi));
    return r;
}
__device__ __forceinline__ void unpack2(ull v, float& lo, float& hi) {
    asm("mov.b64 {%0, %1}, %2;" : "=f"(lo), "=f"(hi) : "l"(v));
}

__global__ __launch_bounds__(256, 1)
void patch_embed_kernel(const float* __restrict__ xyz,
                        const float* __restrict__ centers,
                        const int*   __restrict__ idx_knn,
                        const float* __restrict__ W1, const float* __restrict__ b1,
                        const float* __restrict__ W2, const float* __restrict__ b2,
                        const float* __restrict__ W3, const float* __restrict__ b3,
                        float* __restrict__ out)
{
    extern __shared__ float s[];
    const int t = threadIdx.x;

    // ---- One-time per CTA: stage weights into SMEM (coalesced gmem reads) ----
    if (t < 192) {                       // W1 (64,3) -> transposed [3][64]
        int c = t / 64, o = t % 64;
        s[OFF_W1 + t] = W1[o * 3 + c];
    }
    if (t < 64)  s[OFF_B1 + t] = b1[t];
    if (t < 128) s[OFF_B2 + t] = b2[t];
    s[OFF_B3 + t] = b3[t];
    for (int i = t; i < 128 * 64; i += 256) {   // W2 (128,64) -> [c][o]
        int o = i >> 6, c = i & 63;
        s[OFF_W2 + c * W2ROW + o] = W2[i];
    }
    for (int i = t; i < 256 * 128; i += 256) {  // W3 (256,128) -> [c][o]
        int o = i >> 7, c = i & 127;
        s[OFF_W3 + c * W3ROW + o] = W3[i];
    }
    __syncthreads();

    const int w = t >> 5, l = t & 31;
    const int g = w & 3, h = w >> 2;     // g: 8-point group, h: channel half
    const int p = l & 7, q = l >> 3;     // p: point-in-octet, q: pair group
    const int pt = g * 8 + p;

    for (int ci = 0; ci < NC_PER_CTA; ci++) {
        const int cid = blockIdx.x * NC_PER_CTA + ci;   // global center id
        const int bb  = cid >> 11;                      // batch (M=2048)

        // ---------- Phase 1: gather + center-sub + layer1 (3 -> 64, relu) ----------
        {
            const int pp = t & 31, cg = t >> 5;
            const int idx = idx_knn[cid * KNN + pp];
            const float* xp = xyz + (bb * NPTS + idx) * 3;
            const float cx = centers[cid * 3 + 0];
            const float cy = centers[cid * 3 + 1];
            const float cz = centers[cid * 3 + 2];
            const float lx = xp[0] - cx, ly = xp[1] - cy, lz = xp[2] - cz;
            #pragma unroll
            for (int i = 0; i < 8; i++) {
                const int ch = cg * 8 + i;
                float v = s[OFF_B1 + ch]
                        + lx * s[OFF_W1 + ch]
                        + ly * s[OFF_W1 + 64 + ch]
                        + lz * s[OFF_W1 + 128 + ch];
                s[OFF_H1 + pp * H1ROW + ch] = fmaxf(v, 0.0f);
            }
        }
        __syncthreads();

        // ---------- Phase 2: layer2 (64 -> 128, relu) ----------
        // warp covers 8 points x 64 channels; lane: 1 point x 8 ch-pairs
        {
            ull acc[8];
            const float2* b2p = (const float2*)(s + OFF_B2);
            #pragma unroll
            for (int j = 0; j < 8; j++) {
                float2 bv = b2p[32 * h + 8 * q + j];
                acc[j] = pack2(bv.x, bv.y);
            }
            const float4* h1row = (const float4*)(s + OFF_H1 + pt * H1ROW);
            #pragma unroll
            for (int c4 = 0; c4 < 16; c4++) {
                float4 hv = h1row[c4];
                #pragma unroll
                for (int cc = 0; cc < 4; cc++) {
                    const float hc = (&hv.x)[cc];
                    const ull hp = pack2(hc, hc);
                    const ulonglong2* wr =
                        (const ulonglong2*)(s + OFF_W2 + (c4 * 4 + cc) * W2ROW)
                        + (16 * h + 4 * q);
                    #pragma unroll
                    for (int j2 = 0; j2 < 4; j2++) {
                        ulonglong2 wv = wr[j2];
                        acc[2 * j2]     = fma2(hp, wv.x, acc[2 * j2]);
                        acc[2 * j2 + 1] = fma2(hp, wv.y, acc[2 * j2 + 1]);
                    }
                }
            }
            #pragma unroll
            for (int j = 0; j < 8; j++) {
                float lo, hi; unpack2(acc[j], lo, hi);
                const int pair = 32 * h + 8 * q + j;
                ((float2*)(s + OFF_H2 + pt * H2ROW))[pair] =
                    make_float2(fmaxf(lo, 0.0f), fmaxf(hi, 0.0f));
            }
        }
        __syncthreads();

        // ---------- Phase 3: layer3 (128 -> 256) + max over K ----------
        // warp covers 8 points x 128 channels; lane: 1 point x 16 ch-pairs
        {
            ull acc[16];
            #pragma unroll
            for (int j = 0; j < 16; j++) acc[j] = 0ull;

            const float4* h2row = (const float4*)(s + OFF_H2 + pt * H2ROW);
            #pragma unroll
            for (int c4 = 0; c4 < 32; c4++) {
                float4 hv = h2row[c4];
                #pragma unroll
                for (int cc = 0; cc < 4; cc++) {
                    const float hc = (&hv.x)[cc];
                    const ull hp = pack2(hc, hc);
                    const ulonglong2* wr =
                        (const ulonglong2*)(s + OFF_W3 + (c4 * 4 + cc) * W3ROW)
                        + (32 * h + 8 * q);
                    #pragma unroll
                    for (int j2 = 0; j2 < 8; j2++) {
                        ulonglong2 wv = wr[j2];
                        acc[2 * j2]     = fma2(hp, wv.x, acc[2 * j2]);
                        acc[2 * j2 + 1] = fma2(hp, wv.y, acc[2 * j2 + 1]);
                    }
                }
            }

            // reduce max over the 8 points (octet xor-shuffle), stash partials
            #pragma unroll
            for (int j = 0; j < 16; j++) {
                float lo, hi; unpack2(acc[j], lo, hi);
                #pragma unroll
                for (int d = 1; d < 8; d <<= 1) {
                    lo = fmaxf(lo, __shfl_xor_sync(0xffffffffu, lo, d));
                    hi = fmaxf(hi, __shfl_xor_sync(0xffffffffu, hi, d));
                }
                if (p == 0) {
                    const int pair = 64 * h + 16 * q + j;
                    ((float2*)(s + OFF_OUTP))[g * 128 + pair] = make_float2(lo, hi);
                }
            }
        }
        __syncthreads();

        // ---------- Epilogue: combine 4 point-groups, add bias, store ----------
        if (t < 128) {
            const float2* op = (const float2*)(s + OFF_OUTP);
            float2 v = op[t];
            #pragma unroll
            for (int gg = 1; gg < 4; gg++) {
                float2 u = op[gg * 128 + t];
                v.x = fmaxf(v.x, u.x);
                v.y = fmaxf(v.y, u.y);
            }
            v.x += s[OFF_B3 + 2 * t];
            v.y += s[OFF_B3 + 2 * t + 1];
            ((float2*)out)[cid * 128 + t] = v;
        }
        // no trailing sync needed: next iteration has 2 syncs before OUTP reuse
    }
}

extern "C" void kernel_launch(void* const* d_in, const int* in_sizes, int n_in,
                              void* d_out, int out_size)
{
    const float* xyz     = (const float*)d_in[0];
    const float* centers = (const float*)d_in[1];
    const int*   idx_knn = (const int*)  d_in[2];
    const float* W1      = (const float*)d_in[3];
    const float* b1      = (const float*)d_in[4];
    const float* W2      = (const float*)d_in[5];
    const float* b2      = (const float*)d_in[6];
    const float* W3      = (const float*)d_in[7];
    const float* b3      = (const float*)d_in[8];
    float* out = (float*)d_out;

    cudaFuncSetAttribute(patch_embed_kernel,
                         cudaFuncAttributeMaxDynamicSharedMemorySize, SMEM_BYTES);

    const int n_centers = NB * MC;                      // 16384
    const int grid = n_centers / NC_PER_CTA;            // 2048
    patch_embed_kernel<<<grid, 256, SMEM_BYTES>>>(
        xyz, centers, idx_knn, W1, b1, W2, b2, W3, b3, out);
}

// round 3
// speedup vs baseline: 2.0355x; 2.0355x over previous
#include <cuda_runtime.h>

// Problem constants
#define NB     8
#define NPTS   16384
#define MC     2048
#define KNN    32
#define NC_PER_CTA 8          // centers per CTA (4 iterations x 2 centers)

// Shared row strides (floats). All multiples of 4 (16B alignment), and
// 8*stride % 32 == 0 so per-octet act loads are pure broadcast.
#define H1S 68                // 64 used
#define H2S 132               // 128 used
#define W2S 132               // 128 used
#define W3S 260               // 256 used

// Shared memory layout (float offsets)
#define OFF_W1   0                        // [3][64] transposed W1
#define OFF_B1   192
#define OFF_B2   256
#define OFF_B3   384
#define OFF_W2   640                      // [64][W2S]  (c-major)
#define OFF_W3   (OFF_W2 + 64*W2S)        // [128][W3S] (c-major)
#define OFF_H1   (OFF_W3 + 128*W3S)       // [2][32][H1S]
#define OFF_H2   (OFF_H1 + 2*32*H1S)      // [2][32][H2S]
#define SMEM_FLOATS (OFF_H2 + 2*32*H2S)
#define SMEM_BYTES  (SMEM_FLOATS * 4)     // 220,672 B < 227 KB

typedef unsigned long long ull;

__device__ __forceinline__ ull fma2(ull a, ull b, ull c) {
    ull d;
    asm("fma.rn.f32x2 %0, %1, %2, %3;" : "=l"(d) : "l"(a), "l"(b), "l"(c));
    return d;
}
__device__ __forceinline__ ull pack2(float lo, float hi) {
    ull r;
    asm("mov.b64 %0, {%1, %2};" : "=l"(r) : "f"(lo), "f"(hi));
    return r;
}
__device__ __forceinline__ void unpack2(ull v, float& lo, float& hi) {
    asm("mov.b64 {%0, %1}, %2;" : "=f"(lo), "=f"(hi) : "l"(v));
}

// Warp-tile GEMM: 32 pts x 64 outch, K = KDIM.
// Lane (pt_g = l>>3 in [0,4), oc_g = l&7 in [0,8)) owns pts [pt_g*8, +8)
// and outch {ob + oc_g*4 + 0..3} u {ob + 32 + oc_g*4 + 0..3}.
// acc[i][0..1] = first 4 oc (2 f32x2 pairs), acc[i][2..3] = second 4 oc.
template<int KDIM>
__device__ __forceinline__ void mlp_tile(const float* __restrict__ s,
                                         int abase, int astride,
                                         int wbase, int wstride, int ob,
                                         int pt_g, int oc_g, ull acc[8][4])
{
    const int arow0 = abase + pt_g * 8 * astride;
    const int wcol0 = wbase + ob + oc_g * 4;
    #pragma unroll 1
    for (int c4 = 0; c4 < KDIM / 4; c4++) {
        float4 a[8];
        #pragma unroll
        for (int i = 0; i < 8; i++)
            a[i] = *(const float4*)(s + arow0 + i * astride + c4 * 4);
        #pragma unroll
        for (int kk = 0; kk < 4; kk++) {
            const float* wrow = s + wcol0 + (c4 * 4 + kk) * wstride;
            const ulonglong2 w0 = *(const ulonglong2*)(wrow);
            const ulonglong2 w1 = *(const ulonglong2*)(wrow + 32);
            #pragma unroll
            for (int i = 0; i < 8; i++) {
                const float av = (&a[i].x)[kk];
                const ull ap = pack2(av, av);
                acc[i][0] = fma2(ap, w0.x, acc[i][0]);
                acc[i][1] = fma2(ap, w0.y, acc[i][1]);
                acc[i][2] = fma2(ap, w1.x, acc[i][2]);
                acc[i][3] = fma2(ap, w1.y, acc[i][3]);
            }
        }
    }
}

__global__ __launch_bounds__(256, 1)
void patch_embed_kernel(const float* __restrict__ xyz,
                        const float* __restrict__ centers,
                        const int*   __restrict__ idx_knn,
                        const float* __restrict__ W1, const float* __restrict__ b1,
                        const float* __restrict__ W2, const float* __restrict__ b2,
                        const float* __restrict__ W3, const float* __restrict__ b3,
                        float* __restrict__ out)
{
    extern __shared__ float s[];
    const int t = threadIdx.x;

    // ---- Stage weights into SMEM (coalesced) ----
    if (t < 192) {                        // W1 (64,3) -> [3][64]
        int c = t / 64, o = t % 64;
        s[OFF_W1 + t] = W1[o * 3 + c];
    }
    if (t < 64)  s[OFF_B1 + t] = b1[t];
    if (t < 128) s[OFF_B2 + t] = b2[t];
    s[OFF_B3 + t] = b3[t];
    for (int i = t; i < 128 * 64; i += 256) {   // W2 (128,64) -> [c][o]
        int o = i >> 6, c = i & 63;
        s[OFF_W2 + c * W2S + o] = W2[i];
    }
    for (int i = t; i < 256 * 128; i += 256) {  // W3 (256,128) -> [c][o]
        int o = i >> 7, c = i & 127;
        s[OFF_W3 + c * W3S + o] = W3[i];
    }
    __syncthreads();

    const int w = t >> 5, l = t & 31;
    const int cg = w >> 2;                // center select within pair (0/1)
    const int wc = w & 3;                 // oc-tile index
    const int pt_g = l >> 3, oc_g = l & 7;
    const int h1b = OFF_H1 + cg * (32 * H1S);
    const int h2b = OFF_H2 + cg * (32 * H2S);

    // phase-1 indexing (independent of warp roles)
    const int p1_c  = t >> 7;             // which of the 2 centers
    const int p1_pp = t & 31;             // point
    const int p1_cg = (t >> 5) & 3;       // 16-channel group

    for (int ci = 0; ci < NC_PER_CTA / 2; ci++) {
        const int cbase = blockIdx.x * NC_PER_CTA + ci * 2;

        // -------- Phase 1: gather + center-sub + layer1 (3->64, relu) --------
        {
            const int cid = cbase + p1_c;
            const int bb  = cid >> 11;
            const int idx = idx_knn[cid * KNN + p1_pp];
            const float* xp = xyz + (bb * NPTS + idx) * 3;
            const float lx = xp[0] - centers[cid * 3 + 0];
            const float ly = xp[1] - centers[cid * 3 + 1];
            const float lz = xp[2] - centers[cid * 3 + 2];
            float* h1row = s + OFF_H1 + (p1_c * 32 + p1_pp) * H1S;
            #pragma unroll
            for (int ii = 0; ii < 16; ii++) {
                const int ch = p1_cg * 16 + ii;
                float v = s[OFF_B1 + ch]
                        + lx * s[OFF_W1 + ch]
                        + ly * s[OFF_W1 + 64 + ch]
                        + lz * s[OFF_W1 + 128 + ch];
                h1row[ch] = fmaxf(v, 0.0f);
            }
        }
        __syncthreads();

        // -------- Phase 2: layer2 (64->128, relu), 2 warps per center --------
        if (wc < 2) {
            const int ob = wc * 64;
            ull acc[8][4];
            {
                const float4 bv0 = *(const float4*)(s + OFF_B2 + ob + oc_g * 4);
                const float4 bv1 = *(const float4*)(s + OFF_B2 + ob + 32 + oc_g * 4);
                const ull p0 = pack2(bv0.x, bv0.y), p1 = pack2(bv0.z, bv0.w);
                const ull p2 = pack2(bv1.x, bv1.y), p3 = pack2(bv1.z, bv1.w);
                #pragma unroll
                for (int i = 0; i < 8; i++) {
                    acc[i][0] = p0; acc[i][1] = p1;
                    acc[i][2] = p2; acc[i][3] = p3;
                }
            }
            mlp_tile<64>(s, h1b, H1S, OFF_W2, W2S, ob, pt_g, oc_g, acc);
            #pragma unroll
            for (int i = 0; i < 8; i++) {
                const int pt = pt_g * 8 + i;
                float a0, a1, a2, a3, a4, a5, a6, a7;
                unpack2(acc[i][0], a0, a1); unpack2(acc[i][1], a2, a3);
                unpack2(acc[i][2], a4, a5); unpack2(acc[i][3], a6, a7);
                float* hr = s + h2b + pt * H2S + ob + oc_g * 4;
                *(float4*)(hr)      = make_float4(fmaxf(a0, 0.f), fmaxf(a1, 0.f),
                                                  fmaxf(a2, 0.f), fmaxf(a3, 0.f));
                *(float4*)(hr + 32) = make_float4(fmaxf(a4, 0.f), fmaxf(a5, 0.f),
                                                  fmaxf(a6, 0.f), fmaxf(a7, 0.f));
            }
        }
        __syncthreads();

        // -------- Phase 3: layer3 (128->256) + max over K, 4 warps/center ----
        {
            const int ob = wc * 64;
            ull acc[8][4];
            #pragma unroll
            for (int i = 0; i < 8; i++) {
                acc[i][0] = 0ull; acc[i][1] = 0ull;
                acc[i][2] = 0ull; acc[i][3] = 0ull;
            }
            mlp_tile<128>(s, h2b, H2S, OFF_W3, W3S, ob, pt_g, oc_g, acc);

            // in-lane max over this lane's 8 points
            float m[8];
            unpack2(acc[0][0], m[0], m[1]); unpack2(acc[0][1], m[2], m[3]);
            unpack2(acc[0][2], m[4], m[5]); unpack2(acc[0][3], m[6], m[7]);
            #pragma unroll
            for (int i = 1; i < 8; i++) {
                float lo, hi;
                unpack2(acc[i][0], lo, hi); m[0] = fmaxf(m[0], lo); m[1] = fmaxf(m[1], hi);
                unpack2(acc[i][1], lo, hi); m[2] = fmaxf(m[2], lo); m[3] = fmaxf(m[3], hi);
                unpack2(acc[i][2], lo, hi); m[4] = fmaxf(m[4], lo); m[5] = fmaxf(m[5], hi);
                unpack2(acc[i][3], lo, hi); m[6] = fmaxf(m[6], lo); m[7] = fmaxf(m[7], hi);
            }
            // cross-lane max over the 4 pt-groups (lane bits 3 and 4)
            #pragma unroll
            for (int j = 0; j < 8; j++) {
                m[j] = fmaxf(m[j], __shfl_xor_sync(0xffffffffu, m[j], 8));
                m[j] = fmaxf(m[j], __shfl_xor_sync(0xffffffffu, m[j], 16));
            }
            if (pt_g == 0) {
                const int cid = cbase + cg;
                const int oc0 = ob + oc_g * 4;
                float* op = out + cid * 256 + oc0;
                *(float4*)(op)      = make_float4(m[0] + s[OFF_B3 + oc0],
                                                  m[1] + s[OFF_B3 + oc0 + 1],
                                                  m[2] + s[OFF_B3 + oc0 + 2],
                                                  m[3] + s[OFF_B3 + oc0 + 3]);
                *(float4*)(op + 32) = make_float4(m[4] + s[OFF_B3 + oc0 + 32],
                                                  m[5] + s[OFF_B3 + oc0 + 33],
                                                  m[6] + s[OFF_B3 + oc0 + 34],
                                                  m[7] + s[OFF_B3 + oc0 + 35]);
            }
        }
        // no trailing sync needed: next phase-1 touches only H1 (not H2),
        // and the post-phase-1 sync orders H2 reuse.
    }
}

extern "C" void kernel_launch(void* const* d_in, const int* in_sizes, int n_in,
                              void* d_out, int out_size)
{
    const float* xyz     = (const float*)d_in[0];
    const float* centers = (const float*)d_in[1];
    const int*   idx_knn = (const int*)  d_in[2];
    const float* W1      = (const float*)d_in[3];
    const float* b1      = (const float*)d_in[4];
    const float* W2      = (const float*)d_in[5];
    const float* b2      = (const float*)d_in[6];
    const float* W3      = (const float*)d_in[7];
    const float* b3      = (const float*)d_in[8];
    float* out = (float*)d_out;

    cudaFuncSetAttribute(patch_embed_kernel,
                         cudaFuncAttributeMaxDynamicSharedMemorySize, SMEM_BYTES);

    const int grid = (NB * MC) / NC_PER_CTA;            // 2048
    patch_embed_kernel<<<grid, 256, SMEM_BYTES>>>(
        xyz, centers, idx_knn, W1, b1, W2, b2, W3, b3, out);
}

// round 15
// speedup vs baseline: 2.2582x; 1.1094x over previous
#include <cuda_runtime.h>

// Problem constants
#define NB     8
#define NPTS   16384
#define MC     2048
#define KNN    32
#define NC_PER_CTA 8          // centers per CTA (4 iterations x 2 groups)

// Shared row strides (floats). Multiples of 4 (16B alignment); 8*stride%32==0
// so per-octet activation loads are pure broadcast.
#define H1S 68                // 64 used
#define H2S 132               // 128 used
#define W2S 132               // 128 used
#define W3S 260               // 256 used

// Shared memory layout (float offsets)
#define OFF_W1   0                        // [3][64] transposed W1
#define OFF_B1   192
#define OFF_B2   256
#define OFF_B3   384
#define OFF_W2   640                      // [64][W2S]  (c-major)
#define OFF_W3   (OFF_W2 + 64*W2S)        // [128][W3S] (c-major)
#define OFF_H1   (OFF_W3 + 128*W3S)       // [2][32][H1S]
#define OFF_H2   (OFF_H1 + 2*32*H1S)      // [2][32][H2S]
#define SMEM_FLOATS (OFF_H2 + 2*32*H2S)
#define SMEM_BYTES  (SMEM_FLOATS * 4)     // 220,672 B < 227 KB

typedef unsigned long long ull;

__device__ __forceinline__ ull fma2(ull a, ull b, ull c) {
    ull d;
    asm("fma.rn.f32x2 %0, %1, %2, %3;" : "=l"(d) : "l"(a), "l"(b), "l"(c));
    return d;
}
__device__ __forceinline__ ull pack2(float lo, float hi) {
    ull r;
    asm("mov.b64 %0, {%1, %2};" : "=l"(r) : "f"(lo), "f"(hi));
    return r;
}
__device__ __forceinline__ void unpack2(ull v, float& lo, float& hi) {
    asm("mov.b64 {%0, %1}, %2;" : "=f"(lo), "=f"(hi) : "l"(v));
}
// Named barrier for one 128-thread group (ids 1 and 2).
__device__ __forceinline__ void gbar(int g) {
    asm volatile("bar.sync %0, 128;" :: "r"(g + 1) : "memory");
}

__global__ __launch_bounds__(256, 1)
void patch_embed_kernel(const float* __restrict__ xyz,
                        const float* __restrict__ centers,
                        const int*   __restrict__ idx_knn,
                        const float* __restrict__ W1, const float* __restrict__ b1,
                        const float* __restrict__ W2, const float* __restrict__ b2,
                        const float* __restrict__ W3, const float* __restrict__ b3,
                        float* __restrict__ out)
{
    extern __shared__ float s[];
    const int t = threadIdx.x;

    // ---- Stage weights into SMEM (coalesced) ----
    if (t < 192) {                        // W1 (64,3) -> [3][64]
        int c = t / 64, o = t % 64;
        s[OFF_W1 + t] = W1[o * 3 + c];
    }
    if (t < 64)  s[OFF_B1 + t] = b1[t];
    if (t < 128) s[OFF_B2 + t] = b2[t];
    s[OFF_B3 + t] = b3[t];
    for (int i = t; i < 128 * 64; i += 256) {   // W2 (128,64) -> [c][o]
        int o = i >> 6, c = i & 63;
        s[OFF_W2 + c * W2S + o] = W2[i];
    }
    for (int i = t; i < 256 * 128; i += 256) {  // W3 (256,128) -> [c][o]
        int o = i >> 7, c = i & 127;
        s[OFF_W3 + c * W3S + o] = W3[i];
    }
    __syncthreads();

    // Group decomposition: group g = t>>7 (one center each, 4 warps on SMSP 0-3)
    const int g  = t >> 7;
    const int tg = t & 127;               // thread id within group
    const int wg = tg >> 5;               // warp within group (0..3)
    const int l  = t & 31;
    const int pt_g = l >> 3, oc_g = l & 7;
    const int h1b = OFF_H1 + g * (32 * H1S);
    const int h2b = OFF_H2 + g * (32 * H2S);

    // phase-1 indexing within group: 32 pts x 4 x (16 channels)
    const int p1_pp = tg & 31;
    const int p1_cg = tg >> 5;

    for (int ci = 0; ci < NC_PER_CTA / 2; ci++) {
        const int cid = blockIdx.x * NC_PER_CTA + ci * 2 + g;
        const int bb  = cid >> 11;

        // -------- Phase 1: gather + center-sub + layer1 (3->64, relu) --------
        {
            const int idx = idx_knn[cid * KNN + p1_pp];
            const float* xp = xyz + (bb * NPTS + idx) * 3;
            const float lx = xp[0] - centers[cid * 3 + 0];
            const float ly = xp[1] - centers[cid * 3 + 1];
            const float lz = xp[2] - centers[cid * 3 + 2];
            float* h1row = s + h1b + p1_pp * H1S;
            #pragma unroll
            for (int ii = 0; ii < 16; ii++) {
                const int ch = p1_cg * 16 + ii;
                float v = s[OFF_B1 + ch]
                        + lx * s[OFF_W1 + ch]
                        + ly * s[OFF_W1 + 64 + ch]
                        + lz * s[OFF_W1 + 128 + ch];
                h1row[ch] = fmaxf(v, 0.0f);
            }
        }
        gbar(g);

        // -------- Phase 2: layer2 (64->128, relu), 4 warps x 32 oc ----------
        {
            const int ob = wg * 32;                 // 32 outch per warp
            const int oc0 = ob + oc_g * 4;          // this lane's 4 outch
            ull acc[8][2];
            {
                const float4 bv = *(const float4*)(s + OFF_B2 + oc0);
                const ull p0 = pack2(bv.x, bv.y), p1 = pack2(bv.z, bv.w);
                #pragma unroll
                for (int i = 0; i < 8; i++) { acc[i][0] = p0; acc[i][1] = p1; }
            }
            const int arow0 = h1b + pt_g * 8 * H1S;
            #pragma unroll 1
            for (int c4 = 0; c4 < 16; c4++) {
                float4 a[8];
                #pragma unroll
                for (int i = 0; i < 8; i++)
                    a[i] = *(const float4*)(s + arow0 + i * H1S + c4 * 4);
                #pragma unroll
                for (int kk = 0; kk < 4; kk++) {
                    const ulonglong2 wv = *(const ulonglong2*)
                        (s + OFF_W2 + (c4 * 4 + kk) * W2S + oc0);
                    #pragma unroll
                    for (int i = 0; i < 8; i++) {
                        const float av = (&a[i].x)[kk];
                        const ull ap = pack2(av, av);
                        acc[i][0] = fma2(ap, wv.x, acc[i][0]);
                        acc[i][1] = fma2(ap, wv.y, acc[i][1]);
                    }
                }
            }
            #pragma unroll
            for (int i = 0; i < 8; i++) {
                float a0, a1, a2, a3;
                unpack2(acc[i][0], a0, a1); unpack2(acc[i][1], a2, a3);
                float* hr = s + h2b + (pt_g * 8 + i) * H2S + oc0;
                *(float4*)hr = make_float4(fmaxf(a0, 0.f), fmaxf(a1, 0.f),
                                           fmaxf(a2, 0.f), fmaxf(a3, 0.f));
            }
        }
        gbar(g);

        // -------- Phase 3: layer3 (128->256) + max over K, 4 warps x 64 oc ---
        {
            const int ob = wg * 64;
            ull acc[8][4];
            #pragma unroll
            for (int i = 0; i < 8; i++) {
                acc[i][0] = 0ull; acc[i][1] = 0ull;
                acc[i][2] = 0ull; acc[i][3] = 0ull;
            }
            const int arow0 = h2b + pt_g * 8 * H2S;
            const int wcol0 = OFF_W3 + ob + oc_g * 4;
            #pragma unroll 1
            for (int c4 = 0; c4 < 32; c4++) {
                float4 a[8];
                #pragma unroll
                for (int i = 0; i < 8; i++)
                    a[i] = *(const float4*)(s + arow0 + i * H2S + c4 * 4);
                #pragma unroll
                for (int kk = 0; kk < 4; kk++) {
                    const float* wrow = s + wcol0 + (c4 * 4 + kk) * W3S;
                    const ulonglong2 w0 = *(const ulonglong2*)(wrow);
                    const ulonglong2 w1 = *(const ulonglong2*)(wrow + 32);
                    #pragma unroll
                    for (int i = 0; i < 8; i++) {
                        const float av = (&a[i].x)[kk];
                        const ull ap = pack2(av, av);
                        acc[i][0] = fma2(ap, w0.x, acc[i][0]);
                        acc[i][1] = fma2(ap, w0.y, acc[i][1]);
                        acc[i][2] = fma2(ap, w1.x, acc[i][2]);
                        acc[i][3] = fma2(ap, w1.y, acc[i][3]);
                    }
                }
            }

            // in-lane max over this lane's 8 points
            float m[8];
            unpack2(acc[0][0], m[0], m[1]); unpack2(acc[0][1], m[2], m[3]);
            unpack2(acc[0][2], m[4], m[5]); unpack2(acc[0][3], m[6], m[7]);
            #pragma unroll
            for (int i = 1; i < 8; i++) {
                float lo, hi;
                unpack2(acc[i][0], lo, hi); m[0] = fmaxf(m[0], lo); m[1] = fmaxf(m[1], hi);
                unpack2(acc[i][1], lo, hi); m[2] = fmaxf(m[2], lo); m[3] = fmaxf(m[3], hi);
                unpack2(acc[i][2], lo, hi); m[4] = fmaxf(m[4], lo); m[5] = fmaxf(m[5], hi);
                unpack2(acc[i][3], lo, hi); m[6] = fmaxf(m[6], lo); m[7] = fmaxf(m[7], hi);
            }
            // cross-lane max over the 4 pt-groups (lane bits 3 and 4)
            #pragma unroll
            for (int j = 0; j < 8; j++) {
                m[j] = fmaxf(m[j], __shfl_xor_sync(0xffffffffu, m[j], 8));
                m[j] = fmaxf(m[j], __shfl_xor_sync(0xffffffffu, m[j], 16));
            }
            if (pt_g == 0) {
                const int oc0 = ob + oc_g * 4;
                float* op = out + cid * 256 + oc0;
                *(float4*)(op)      = make_float4(m[0] + s[OFF_B3 + oc0],
                                                  m[1] + s[OFF_B3 + oc0 + 1],
                                                  m[2] + s[OFF_B3 + oc0 + 2],
                                                  m[3] + s[OFF_B3 + oc0 + 3]);
                *(float4*)(op + 32) = make_float4(m[4] + s[OFF_B3 + oc0 + 32],
                                                  m[5] + s[OFF_B3 + oc0 + 33],
                                                  m[6] + s[OFF_B3 + oc0 + 34],
                                                  m[7] + s[OFF_B3 + oc0 + 35]);
            }
        }
        gbar(g);   // phase-3 H2 reads vs next iter phase-2 H2 writes
    }
}

extern "C" void kernel_launch(void* const* d_in, const int* in_sizes, int n_in,
                              void* d_out, int out_size)
{
    const float* xyz     = (const float*)d_in[0];
    const float* centers = (const float*)d_in[1];
    const int*   idx_knn = (const int*)  d_in[2];
    const float* W1      = (const float*)d_in[3];
    const float* b1      = (const float*)d_in[4];
    const float* W2      = (const float*)d_in[5];
    const float* b2      = (const float*)d_in[6];
    const float* W3      = (const float*)d_in[7];
    const float* b3      = (const float*)d_in[8];
    float* out = (float*)d_out;

    cudaFuncSetAttribute(patch_embed_kernel,
                         cudaFuncAttributeMaxDynamicSharedMemorySize, SMEM_BYTES);

    const int grid = (NB * MC) / NC_PER_CTA;            // 2048
    patch_embed_kernel<<<grid, 256, SMEM_BYTES>>>(
        xyz, centers, idx_knn, W1, b1, W2, b2, W3, b3, out);
}